// round 16
// baseline (speedup 1.0000x reference)
#include <cuda_runtime.h>
#include <cuda_bf16.h>
#include <cuda_fp16.h>
#include <math.h>
#include <stdint.h>

#define N_NODES   100000
#define N_EDGES   1600000
#define D         128
#define NSUB      8                                     // sub-counters per node
#define SCAN_BS   1024
#define SCAN_NB   ((N_NODES + SCAN_BS - 1) / SCAN_BS)   // 98
#define EDGE_BLKS ((N_EDGES + 255) / 256)               // 6250
#define WARP_BLKS ((N_NODES * 32 + 255) / 256)          // 12500
#define WPREP_BLKS 64                                   // 16384 items / 256

// ---------------------------------------------------------------------------
// Scratch (__device__ globals; referenced ONLY from device code).
// Self-cleaning: g_scnt is zeroed inside scan right after being read
// (globals start zeroed -> call 1 covered; every call leaves them zero).
// g_sflag is zeroed by kernel 1 of every call (before scan runs).
// ---------------------------------------------------------------------------
__device__ __half g_x016 [(size_t)N_NODES * D];  // emb[cncpt[v]] fp16 (25.6 MB)
__device__ __half g_agg16[(size_t)N_NODES * D];  // agg output fp16    (25.6 MB)
__device__ __half g_h16  [(size_t)N_NODES * D];  // layer-1 out fp16   (25.6 MB)
// fp16 weights, packed u32 (fp16x2 along k): layout [mat(2)][f(128)][kpair(64)]
__device__ uint32_t g_Wpk16[2 * 128 * 64];
__device__ int g_scnt   [N_NODES * NSUB];  // contention-split histogram (3.2 MB)
__device__ int g_subbase[N_NODES * NSUB];  // csr base per (node, sub)   (3.2 MB)
__device__ int g_rowptr [N_NODES + 1];
__device__ int g_rank   [N_EDGES];         // edge's rank within (dst, sub)
__device__ int g_sflag  [SCAN_NB];          // lookback flags: 0 = pending, total+1
__device__ int g_csrsrc [N_EDGES];

// ---------------------------------------------------------------------------
// Kernel 1: W->fp16 convert + contention-split histogram(rank capture) +
// x0 gather, all independent workloads in one launch.
//   blocks [0, WPREP_BLKS):          W convert (block 0 also zeros sflag)
//   blocks [WPREP_BLKS, +EDGE_BLKS): rank[e] = atomicAdd(&scnt[dst*8+(e&7)],1)
//   remaining WARP_BLKS blocks:      g_x016[v] = fp16(emb[cncpt[v]])
// Splitting each node's counter 8 ways cuts L2 same-address atomic
// serialization (avg 16 ops/addr -> 2), which pinned the old hist at ~24 us.
// ---------------------------------------------------------------------------
__global__ void prep_hist_gather_kernel(const float* __restrict__ W1,
                                        const float* __restrict__ W2,
                                        const int* __restrict__ dst,
                                        const int* __restrict__ cncpt,
                                        const float* __restrict__ emb) {
    if (blockIdx.x < WPREP_BLKS) {
        if (blockIdx.x == 0 && threadIdx.x < SCAN_NB)
            g_sflag[threadIdx.x] = 0;
        int i = blockIdx.x * blockDim.x + threadIdx.x;   // < 16384
        int mat = i >> 13, rem = i & 8191;
        int f = rem >> 6, p = rem & 63;
        const float* W = mat ? W2 : W1;
        float w0 = __ldg(W + f * D + 2 * p);
        float w1 = __ldg(W + f * D + 2 * p + 1);
        __half2 h = __floats2half2_rn(w0, w1);
        uint32_t hw;
        memcpy(&hw, &h, 4);
        g_Wpk16[(mat * 128 + f) * 64 + p] = hw;
    } else if (blockIdx.x < WPREP_BLKS + EDGE_BLKS) {
        int e = (blockIdx.x - WPREP_BLKS) * blockDim.x + threadIdx.x;
        if (e < N_EDGES) {
            int d = __ldg(dst + e);
            g_rank[e] = atomicAdd(&g_scnt[(d << 3) + (e & (NSUB - 1))], 1);
        }
    } else {
        int node = ((blockIdx.x - WPREP_BLKS - EDGE_BLKS) * blockDim.x + threadIdx.x) >> 5;
        if (node >= N_NODES) return;
        int lane = threadIdx.x & 31;
        int c = __ldg(cncpt + node);
        float4 v = __ldg(reinterpret_cast<const float4*>(emb + (size_t)c * D) + lane);
        __half2 h0 = __floats2half2_rn(v.x, v.y);
        __half2 h1 = __floats2half2_rn(v.z, v.w);
        uint2 w;
        memcpy(&w.x, &h0, 4); memcpy(&w.y, &h1, 4);
        reinterpret_cast<uint2*>(g_x016 + (size_t)node * D)[lane] = w;
    }
}

// ---------------------------------------------------------------------------
// Single-pass scan with decoupled lookback (98 blocks co-resident).
// Thread owns one node: sums its 8 sub-counts (2x int4), zeroes them
// (self-clean), scans node totals, then emits the 8 per-sub base offsets.
// ---------------------------------------------------------------------------
__global__ void scan_kernel() {
    __shared__ int wsum[32];
    __shared__ int s_pref;
    const int t = threadIdx.x, lane = t & 31, wid = t >> 5;
    const int j = blockIdx.x;
    int i = j * SCAN_BS + t;

    int c[NSUB];
    int v = 0;
    if (i < N_NODES) {
        int4 lo = *reinterpret_cast<int4*>(g_scnt + i * NSUB);
        int4 hi = *reinterpret_cast<int4*>(g_scnt + i * NSUB + 4);
        c[0] = lo.x; c[1] = lo.y; c[2] = lo.z; c[3] = lo.w;
        c[4] = hi.x; c[5] = hi.y; c[6] = hi.z; c[7] = hi.w;
        v = c[0] + c[1] + c[2] + c[3] + c[4] + c[5] + c[6] + c[7];
        int4 z = make_int4(0, 0, 0, 0);
        *reinterpret_cast<int4*>(g_scnt + i * NSUB) = z;       // self-clean
        *reinterpret_cast<int4*>(g_scnt + i * NSUB + 4) = z;
    }
    int s = v;
#pragma unroll
    for (int o = 1; o < 32; o <<= 1) {
        int y = __shfl_up_sync(0xffffffffu, s, o);
        if (lane >= o) s += y;
    }
    if (lane == 31) wsum[wid] = s;
    __syncthreads();
    if (wid == 0) {
        int ws = wsum[lane];
#pragma unroll
        for (int o = 1; o < 32; o <<= 1) {
            int y = __shfl_up_sync(0xffffffffu, ws, o);
            if (lane >= o) ws += y;
        }
        wsum[lane] = ws;
    }
    __syncthreads();
    int incl = s + (wid ? wsum[wid - 1] : 0);
    if (t == SCAN_BS - 1)
        atomicExch(&g_sflag[j], incl + 1);
    if (wid == 0) {
        int p = 0;
        for (int k = lane; k < j; k += 32) {
            int f;
            do { f = atomicAdd(&g_sflag[k], 0); } while (f == 0);
            p += f - 1;
        }
#pragma unroll
        for (int o = 16; o; o >>= 1) p += __shfl_xor_sync(0xffffffffu, p, o);
        if (lane == 0) s_pref = p;
    }
    __syncthreads();
    if (i < N_NODES) {
        int rp = s_pref + incl - v;
        g_rowptr[i] = rp;
        int run = rp;
        int sb[NSUB];
#pragma unroll
        for (int k = 0; k < NSUB; k++) { sb[k] = run; run += c[k]; }
        int4 lo = make_int4(sb[0], sb[1], sb[2], sb[3]);
        int4 hi = make_int4(sb[4], sb[5], sb[6], sb[7]);
        *reinterpret_cast<int4*>(g_subbase + i * NSUB) = lo;
        *reinterpret_cast<int4*>(g_subbase + i * NSUB + 4) = hi;
    }
    if (i == 0) g_rowptr[N_NODES] = N_EDGES;
}

// ---------------------------------------------------------------------------
// fill_csr, ATOMIC-FREE: position = subbase[dst*8+(e&7)] + rank[e].
// Pure bandwidth: coalesced dst/rank/src reads, L2 subbase gather,
// scattered 4B store.
// ---------------------------------------------------------------------------
__global__ void fill_csr_kernel(const int* __restrict__ src,
                                const int* __restrict__ dst) {
    int e = blockIdx.x * blockDim.x + threadIdx.x;
    if (e >= N_EDGES) return;
    int d = __ldg(dst + e);
    int p = __ldg(g_subbase + (d << 3) + (e & (NSUB - 1))) + __ldg(g_rank + e);
    g_csrsrc[p] = __ldg(src + e);
}

// ---------------------------------------------------------------------------
// CSR gather-aggregation over fp16 rows (256 B): warp per node, lane owns
// features 4l..4l+3 (uint2 = 4 halves); shfl-broadcast indices, 4 row loads
// in flight (1 KB/warp). fp32 accumulate; fp16 output.
// Measured at ~86% of the chip LTS cap — at its roofline, do not touch.
// ---------------------------------------------------------------------------
template <bool FIRST>
__global__ void __launch_bounds__(256) agg16_kernel() {
    int node = (blockIdx.x * blockDim.x + threadIdx.x) >> 5;
    if (node >= N_NODES) return;
    int lane = threadIdx.x & 31;
    const __half* __restrict__ xin = FIRST ? g_x016 : g_h16;
    int beg = __ldg(g_rowptr + node);
    int end = __ldg(g_rowptr + node + 1);

    float4 a0 = make_float4(0.f, 0.f, 0.f, 0.f);
    float4 a1 = make_float4(0.f, 0.f, 0.f, 0.f);
    int e = beg;
    while (e < end) {
        int n = end - e; if (n > 32) n = 32;
        int idx = (lane < n) ? __ldg(g_csrsrc + e + lane) : 0;
        int j = 0;
        for (; j + 4 <= n; j += 4) {
            int s0 = __shfl_sync(0xffffffffu, idx, j);
            int s1 = __shfl_sync(0xffffffffu, idx, j + 1);
            int s2 = __shfl_sync(0xffffffffu, idx, j + 2);
            int s3 = __shfl_sync(0xffffffffu, idx, j + 3);
            uint2 r0 = __ldg(reinterpret_cast<const uint2*>(xin + (size_t)s0 * D) + lane);
            uint2 r1 = __ldg(reinterpret_cast<const uint2*>(xin + (size_t)s1 * D) + lane);
            uint2 r2 = __ldg(reinterpret_cast<const uint2*>(xin + (size_t)s2 * D) + lane);
            uint2 r3 = __ldg(reinterpret_cast<const uint2*>(xin + (size_t)s3 * D) + lane);
            float2 f;
            f = __half22float2(*reinterpret_cast<__half2*>(&r0.x)); a0.x += f.x; a0.y += f.y;
            f = __half22float2(*reinterpret_cast<__half2*>(&r0.y)); a0.z += f.x; a0.w += f.y;
            f = __half22float2(*reinterpret_cast<__half2*>(&r1.x)); a1.x += f.x; a1.y += f.y;
            f = __half22float2(*reinterpret_cast<__half2*>(&r1.y)); a1.z += f.x; a1.w += f.y;
            f = __half22float2(*reinterpret_cast<__half2*>(&r2.x)); a0.x += f.x; a0.y += f.y;
            f = __half22float2(*reinterpret_cast<__half2*>(&r2.y)); a0.z += f.x; a0.w += f.y;
            f = __half22float2(*reinterpret_cast<__half2*>(&r3.x)); a1.x += f.x; a1.y += f.y;
            f = __half22float2(*reinterpret_cast<__half2*>(&r3.y)); a1.z += f.x; a1.w += f.y;
        }
        for (; j < n; j++) {
            int s0 = __shfl_sync(0xffffffffu, idx, j);
            uint2 r0 = __ldg(reinterpret_cast<const uint2*>(xin + (size_t)s0 * D) + lane);
            float2 f;
            f = __half22float2(*reinterpret_cast<__half2*>(&r0.x)); a0.x += f.x; a0.y += f.y;
            f = __half22float2(*reinterpret_cast<__half2*>(&r0.y)); a0.z += f.x; a0.w += f.y;
        }
        e += n;
    }
    a0.x += a1.x; a0.y += a1.y; a0.z += a1.z; a0.w += a1.w;
    __half2 h0 = __floats2half2_rn(a0.x, a0.y);
    __half2 h1 = __floats2half2_rn(a0.z, a0.w);
    uint2 w;
    memcpy(&w.x, &h0, 4); memcpy(&w.y, &h1, 4);
    reinterpret_cast<uint2*>(g_agg16 + (size_t)node * D)[lane] = w;
}

// ---------------------------------------------------------------------------
// fp16 mma.sync helper (sm_80+ PTX; fp32 accumulate)
// ---------------------------------------------------------------------------
__device__ __forceinline__ void mma16816(float* c, const uint32_t* a,
                                         const uint32_t* b) {
    asm volatile(
        "mma.sync.aligned.m16n8k16.row.col.f32.f16.f16.f32 "
        "{%0,%1,%2,%3}, {%4,%5,%6,%7}, {%8,%9}, {%0,%1,%2,%3};"
        : "+f"(c[0]), "+f"(c[1]), "+f"(c[2]), "+f"(c[3])
        : "r"(a[0]), "r"(a[1]), "r"(a[2]), "r"(a[3]), "r"(b[0]), "r"(b[1]));
}

// ---------------------------------------------------------------------------
// Tensor-core MLP, single-pass fp16 (R14 verified). CTA = 128 nodes x 128
// features, 256 threads, warps 4x2 (32x64 tiles), smem 69632 B -> 2 CTAs/SM.
//   FINAL=false: writes y=relu(agg@W^T+b) to g_h16 (fp16).
//   FINAL=true : fuses out = sigmoid(y . wout + bout).
// ---------------------------------------------------------------------------
template <bool FINAL>
__global__ void __launch_bounds__(256) mlp_mma_kernel(const float* __restrict__ b,
                                                      const float* __restrict__ wout,
                                                      const float* __restrict__ bout,
                                                      float* __restrict__ out) {
    extern __shared__ uint32_t shw[];
    uint32_t* Xs = shw;                // [128][68]
    uint32_t* Ws = shw + 8704;         // [128][68]
    __shared__ float sb[128];
    __shared__ float swout[128];
    __shared__ float nodeSum[128];

    const int t = threadIdx.x;
    const int wid = t >> 5, lane = t & 31;
    const int gbase = blockIdx.x * 128;

    // Stage W (straight copy of packed fp16 weights; L2-resident 32 KB)
    {
        const uint32_t* srcW = g_Wpk16 + (FINAL ? 8192 : 0);
#pragma unroll
        for (int i = 0; i < 32; i++) {
            int idx = t + 256 * i;            // 8192 total
            int f = idx >> 6, p = idx & 63;
            Ws[f * 68 + p] = __ldg(srcW + idx);
        }
    }
    // Stage X: raw uint4 copy of fp16 agg rows (16 uint4 per 256-B row)
#pragma unroll
    for (int i = 0; i < 8; i++) {
        int idx = t + 256 * i;                // 2048 total
        int r = idx >> 4, q = idx & 15;
        int node = gbase + r;
        uint4 v = make_uint4(0u, 0u, 0u, 0u);
        if (node < N_NODES)
            v = *(reinterpret_cast<const uint4*>(g_agg16 + (size_t)node * D) + q);
        *reinterpret_cast<uint4*>(Xs + r * 68 + 4 * q) = v;
    }
    if (t < 128) {
        sb[t] = __ldg(b + t);
        if (FINAL) { swout[t] = __ldg(wout + t); nodeSum[t] = 0.f; }
    }
    __syncthreads();

    const int m0 = (wid >> 1) * 32, n0 = (wid & 1) * 64;
    float acc[2][8][4];
#pragma unroll
    for (int mt = 0; mt < 2; mt++)
#pragma unroll
        for (int nt = 0; nt < 8; nt++)
#pragma unroll
            for (int j = 0; j < 4; j++) acc[mt][nt][j] = 0.f;

    const int lq = lane >> 2, lr = lane & 3;
#pragma unroll
    for (int ks = 0; ks < 8; ks++) {
        const int kp = ks * 8 + lr;
        uint32_t a[2][4];
#pragma unroll
        for (int mt = 0; mt < 2; mt++) {
            int r0i = m0 + mt * 16 + lq;
            a[mt][0] = Xs[r0i * 68 + kp];
            a[mt][1] = Xs[(r0i + 8) * 68 + kp];
            a[mt][2] = Xs[r0i * 68 + kp + 4];
            a[mt][3] = Xs[(r0i + 8) * 68 + kp + 4];
        }
        uint32_t bf[8][2];
#pragma unroll
        for (int nt = 0; nt < 8; nt++) {
            int nr = n0 + nt * 8 + lq;
            bf[nt][0] = Ws[nr * 68 + kp];
            bf[nt][1] = Ws[nr * 68 + kp + 4];
        }
#pragma unroll
        for (int mt = 0; mt < 2; mt++)
#pragma unroll
            for (int nt = 0; nt < 8; nt++)
                mma16816(acc[mt][nt], a[mt], bf[nt]);
    }

    if (!FINAL) {
#pragma unroll
        for (int mt = 0; mt < 2; mt++) {
            int rA = m0 + mt * 16 + lq;
            int nodeA = gbase + rA, nodeB = nodeA + 8;
#pragma unroll
            for (int nt = 0; nt < 8; nt++) {
                int c = n0 + nt * 8 + lr * 2;
                if (nodeA < N_NODES) {
                    __half2 y = __floats2half2_rn(
                        fmaxf(acc[mt][nt][0] + sb[c],     0.f),
                        fmaxf(acc[mt][nt][1] + sb[c + 1], 0.f));
                    *reinterpret_cast<__half2*>(g_h16 + (size_t)nodeA * D + c) = y;
                }
                if (nodeB < N_NODES) {
                    __half2 y = __floats2half2_rn(
                        fmaxf(acc[mt][nt][2] + sb[c],     0.f),
                        fmaxf(acc[mt][nt][3] + sb[c + 1], 0.f));
                    *reinterpret_cast<__half2*>(g_h16 + (size_t)nodeB * D + c) = y;
                }
            }
        }
    } else {
#pragma unroll
        for (int mt = 0; mt < 2; mt++) {
            float pA = 0.f, pB = 0.f;
            int rA = m0 + mt * 16 + lq;
#pragma unroll
            for (int nt = 0; nt < 8; nt++) {
                int c = n0 + nt * 8 + lr * 2;
                pA += fmaxf(acc[mt][nt][0] + sb[c],     0.f) * swout[c]
                    + fmaxf(acc[mt][nt][1] + sb[c + 1], 0.f) * swout[c + 1];
                pB += fmaxf(acc[mt][nt][2] + sb[c],     0.f) * swout[c]
                    + fmaxf(acc[mt][nt][3] + sb[c + 1], 0.f) * swout[c + 1];
            }
            pA += __shfl_xor_sync(0xffffffffu, pA, 1);
            pA += __shfl_xor_sync(0xffffffffu, pA, 2);
            pB += __shfl_xor_sync(0xffffffffu, pB, 1);
            pB += __shfl_xor_sync(0xffffffffu, pB, 2);
            if (lr == 0) {
                atomicAdd(&nodeSum[rA], pA);
                atomicAdd(&nodeSum[rA + 8], pB);
            }
        }
        __syncthreads();
        if (t < 128) {
            int node = gbase + t;
            if (node < N_NODES)
                out[node] = 1.f / (1.f + expf(-(nodeSum[t] + __ldg(bout))));
        }
    }
}

// ---------------------------------------------------------------------------
extern "C" void kernel_launch(void* const* d_in, const int* in_sizes, int n_in,
                              void* d_out, int out_size) {
    const int*   cncpt = (const int*)d_in[0];
    const int*   src   = (const int*)d_in[1];
    const int*   dst   = (const int*)d_in[2];
    const float* emb   = (const float*)d_in[3];
    const float* W1    = (const float*)d_in[4];
    const float* b1    = (const float*)d_in[5];
    const float* W2    = (const float*)d_in[6];
    const float* b2    = (const float*)d_in[7];
    const float* Wout  = (const float*)d_in[8];
    const float* bout  = (const float*)d_in[9];
    float* out = (float*)d_out;

    const int MLP_SMEM = 2 * 8704 * 4;   // 69632 B -> 2 CTAs/SM
    cudaFuncSetAttribute(mlp_mma_kernel<false>, cudaFuncAttributeMaxDynamicSharedMemorySize, MLP_SMEM);
    cudaFuncSetAttribute(mlp_mma_kernel<true>,  cudaFuncAttributeMaxDynamicSharedMemorySize, MLP_SMEM);

    const int MLP_BLKS = (N_NODES + 127) / 128;   // 782

    // 1: W convert + split-histogram(rank capture) + x0 gather, one launch
    prep_hist_gather_kernel<<<WPREP_BLKS + EDGE_BLKS + WARP_BLKS, 256>>>(
        W1, W2, dst, cncpt, emb);
    // 2: scan (self-cleaning sub-counts -> rowptr + per-sub bases)
    scan_kernel<<<SCAN_NB, SCAN_BS>>>();
    // 3: atomic-free CSR fill
    fill_csr_kernel<<<EDGE_BLKS, 256>>>(src, dst);

    // Layer 1
    agg16_kernel<true><<<WARP_BLKS, 256>>>();
    mlp_mma_kernel<false><<<MLP_BLKS, 256, MLP_SMEM>>>(b1, nullptr, nullptr, nullptr);

    // Layer 2 (+ fused sigmoid head)
    agg16_kernel<false><<<WARP_BLKS, 256>>>();
    mlp_mma_kernel<true><<<MLP_BLKS, 256, MLP_SMEM>>>(b2, Wout, bout, out);

    (void)in_sizes; (void)n_in; (void)out_size;
}